// round 1
// baseline (speedup 1.0000x reference)
#include <cuda_runtime.h>

// Problem constants (fixed shapes per reference)
#define T_TOK 500000
#define M_MEN 50000
#define B_BAG 5000
#define V_VOC 100000
#define D_DIM 256
#define K_TYP 100

// Scratch (no allocations allowed)
__device__ float g_men_emb[M_MEN * D_DIM];   // 51.2 MB
__device__ float g_sel[M_MEN];
__device__ float g_att[M_MEN];
__device__ int   g_type_idx[B_BAG];

// ---------------------------------------------------------------------------
// K0: per-bag argmax over typeTensor[b, 0:100]  (one warp per bag)
// ---------------------------------------------------------------------------
__global__ void k0_argmax(const float* __restrict__ typeT, int* __restrict__ tidx) {
    int b    = blockIdx.x * (blockDim.x >> 5) + (threadIdx.x >> 5);
    int lane = threadIdx.x & 31;
    if (b >= B_BAG) return;
    float best = -INFINITY; int bi = K_TYP;
    for (int k = lane; k < K_TYP; k += 32) {
        float v = typeT[(size_t)b * K_TYP + k];
        if (v > best) { best = v; bi = k; }
    }
    #pragma unroll
    for (int off = 16; off; off >>= 1) {
        float ov = __shfl_xor_sync(0xffffffffu, best, off);
        int   oi = __shfl_xor_sync(0xffffffffu, bi,   off);
        if (ov > best || (ov == best && oi < bi)) { best = ov; bi = oi; }
    }
    if (lane == 0) tidx[b] = bi;
}

// ---------------------------------------------------------------------------
// K1: one warp per mention. Gather+mean token embeddings -> men_emb[m],
//     fused dot with linear_weight[type_idx[bag(m)]] -> sel[m].
// ---------------------------------------------------------------------------
__global__ void k1_mention(const int*   __restrict__ feat,
                           const int*   __restrict__ offs,
                           const int*   __restrict__ scope,
                           const float* __restrict__ emb,
                           const float* __restrict__ lw,
                           const int*   __restrict__ tidx_arr) {
    int m    = blockIdx.x * (blockDim.x >> 5) + (threadIdx.x >> 5);
    int lane = threadIdx.x & 31;
    if (m >= M_MEN) return;

    int start = offs[m];
    int end   = (m + 1 < M_MEN) ? offs[m + 1] : T_TOK;

    // bag id: largest b with scope[b] <= m  (scope[0]=0, scope[B]=M)
    int lo = 0, hi = B_BAG;
    while (hi - lo > 1) {
        int mid = (lo + hi) >> 1;
        if (scope[mid] <= m) lo = mid; else hi = mid;
    }
    int t = tidx_arr[lo];

    float4 a0 = make_float4(0.f, 0.f, 0.f, 0.f);
    float4 a1 = make_float4(0.f, 0.f, 0.f, 0.f);
    for (int p = start; p < end; p++) {
        int tok = feat[p];
        const float4* row = (const float4*)(emb + (size_t)tok * D_DIM);
        float4 v0 = row[lane];
        float4 v1 = row[lane + 32];
        a0.x += v0.x; a0.y += v0.y; a0.z += v0.z; a0.w += v0.w;
        a1.x += v1.x; a1.y += v1.y; a1.z += v1.z; a1.w += v1.w;
    }
    float inv = 1.0f / (float)(end - start);
    a0.x *= inv; a0.y *= inv; a0.z *= inv; a0.w *= inv;
    a1.x *= inv; a1.y *= inv; a1.z *= inv; a1.w *= inv;

    float4* mrow = (float4*)(g_men_emb + (size_t)m * D_DIM);
    mrow[lane]      = a0;
    mrow[lane + 32] = a1;

    const float4* w = (const float4*)(lw + (size_t)t * D_DIM);
    float4 w0 = w[lane];
    float4 w1 = w[lane + 32];
    float d = a0.x * w0.x + a0.y * w0.y + a0.z * w0.z + a0.w * w0.w
            + a1.x * w1.x + a1.y * w1.y + a1.z * w1.z + a1.w * w1.w;
    #pragma unroll
    for (int off = 16; off; off >>= 1) d += __shfl_xor_sync(0xffffffffu, d, off);
    if (lane == 0) g_sel[m] = d;
}

// ---------------------------------------------------------------------------
// K2: one warp per bag — segment-stable softmax over sel -> att
// ---------------------------------------------------------------------------
__global__ void k2_softmax(const int* __restrict__ scope) {
    int b    = blockIdx.x * (blockDim.x >> 5) + (threadIdx.x >> 5);
    int lane = threadIdx.x & 31;
    if (b >= B_BAG) return;
    int s = scope[b], e = scope[b + 1];

    float mx = -INFINITY;
    for (int m = s + lane; m < e; m += 32) mx = fmaxf(mx, g_sel[m]);
    #pragma unroll
    for (int off = 16; off; off >>= 1)
        mx = fmaxf(mx, __shfl_xor_sync(0xffffffffu, mx, off));

    float sum = 0.f;
    for (int m = s + lane; m < e; m += 32) sum += expf(g_sel[m] - mx);
    #pragma unroll
    for (int off = 16; off; off >>= 1)
        sum += __shfl_xor_sync(0xffffffffu, sum, off);

    float invs = 1.0f / sum;
    for (int m = s + lane; m < e; m += 32)
        g_att[m] = expf(g_sel[m] - mx) * invs;
}

// ---------------------------------------------------------------------------
// K3: one 256-thread block per bag.
//     bag_emb[col] = sum_m att[m]*men_emb[m,col] (thread=col, coalesced),
//     then out[b,k] = dot(bag_emb, W[k]) via warp-per-k.
// ---------------------------------------------------------------------------
__global__ void k3_bag(const int*   __restrict__ scope,
                       const float* __restrict__ lw,
                       float*       __restrict__ out) {
    int b   = blockIdx.x;
    int tid = threadIdx.x;          // 256 threads
    int s = scope[b], e = scope[b + 1];

    __shared__ float bemb[D_DIM];
    float acc = 0.f;
    for (int m = s; m < e; m++)
        acc += g_att[m] * g_men_emb[(size_t)m * D_DIM + tid];
    bemb[tid] = acc;
    __syncthreads();

    int warp = tid >> 5, lane = tid & 31;
    for (int k = warp; k < K_TYP; k += 8) {
        const float* wr = lw + (size_t)k * D_DIM;
        float p = 0.f;
        #pragma unroll
        for (int j = 0; j < 8; j++)
            p += wr[j * 32 + lane] * bemb[j * 32 + lane];
        #pragma unroll
        for (int off = 16; off; off >>= 1)
            p += __shfl_xor_sync(0xffffffffu, p, off);
        if (lane == 0) out[(size_t)b * K_TYP + k] = p;
    }
}

// ---------------------------------------------------------------------------
extern "C" void kernel_launch(void* const* d_in, const int* in_sizes, int n_in,
                              void* d_out, int out_size) {
    const int*   feature_seq    = (const int*)  d_in[0];   // [T]
    const int*   offset_seq     = (const int*)  d_in[1];   // [M]
    const int*   scope          = (const int*)  d_in[2];   // [B+1]
    const float* typeTensor     = (const float*)d_in[3];   // [B,K]
    const float* word_embedding = (const float*)d_in[4];   // [V,D]
    const float* linear_weight  = (const float*)d_in[5];   // [K,D]
    float*       out            = (float*)d_out;           // [B,K]

    int*   tidx = nullptr;
    cudaGetSymbolAddress((void**)&tidx, g_type_idx);

    // K0: per-bag argmax (8 warps/block)
    k0_argmax<<<(B_BAG + 7) / 8, 256>>>(typeTensor, tidx);

    // K1: per-mention gather/mean + fused selected-type dot (8 warps/block)
    k1_mention<<<(M_MEN + 7) / 8, 256>>>(feature_seq, offset_seq, scope,
                                         word_embedding, linear_weight, tidx);

    // K2: per-bag softmax attention weights
    k2_softmax<<<(B_BAG + 7) / 8, 256>>>(scope);

    // K3: per-bag weighted sum + final projection
    k3_bag<<<B_BAG, 256>>>(scope, linear_weight, out);
}

// round 2
// speedup vs baseline: 1.0052x; 1.0052x over previous
#include <cuda_runtime.h>

#define T_TOK 500000
#define M_MEN 50000
#define B_BAG 5000
#define V_VOC 100000
#define D_DIM 256
#define K_TYP 100

// Scratch (no allocations allowed)
__device__ float g_men_emb[M_MEN * D_DIM];      // 51.2 MB
__device__ float g_sel[M_MEN];
__device__ float g_bag_emb[B_BAG * D_DIM];      // 5.12 MB
__device__ int   g_type_idx[B_BAG];

// ---------------------------------------------------------------------------
// K0: per-bag argmax over typeTensor[b, 0:100]  (one warp per bag)
// ---------------------------------------------------------------------------
__global__ void k0_argmax(const float* __restrict__ typeT, int* __restrict__ tidx) {
    int b    = blockIdx.x * (blockDim.x >> 5) + (threadIdx.x >> 5);
    int lane = threadIdx.x & 31;
    if (b >= B_BAG) return;
    float best = -INFINITY; int bi = K_TYP;
    for (int k = lane; k < K_TYP; k += 32) {
        float v = typeT[(size_t)b * K_TYP + k];
        if (v > best) { best = v; bi = k; }
    }
    #pragma unroll
    for (int off = 16; off; off >>= 1) {
        float ov = __shfl_xor_sync(0xffffffffu, best, off);
        int   oi = __shfl_xor_sync(0xffffffffu, bi,   off);
        if (ov > best || (ov == best && oi < bi)) { best = ov; bi = oi; }
    }
    if (lane == 0) tidx[b] = bi;
}

// ---------------------------------------------------------------------------
// K1: one warp per mention. Gather+mean token embeddings -> men_emb[m],
//     fused dot with linear_weight[type_idx[bag(m)]] -> sel[m].
// ---------------------------------------------------------------------------
__global__ void k1_mention(const int*   __restrict__ feat,
                           const int*   __restrict__ offs,
                           const int*   __restrict__ scope,
                           const float* __restrict__ emb,
                           const float* __restrict__ lw,
                           const int*   __restrict__ tidx_arr) {
    int m    = blockIdx.x * (blockDim.x >> 5) + (threadIdx.x >> 5);
    int lane = threadIdx.x & 31;
    if (m >= M_MEN) return;

    int start = offs[m];
    int end   = (m + 1 < M_MEN) ? offs[m + 1] : T_TOK;

    // bag id: largest b with scope[b] <= m
    int lo = 0, hi = B_BAG;
    while (hi - lo > 1) {
        int mid = (lo + hi) >> 1;
        if (scope[mid] <= m) lo = mid; else hi = mid;
    }
    int t = tidx_arr[lo];

    float4 a0 = make_float4(0.f, 0.f, 0.f, 0.f);
    float4 a1 = make_float4(0.f, 0.f, 0.f, 0.f);

    int p = start;
    // 2-token unroll for MLP (4 independent float4 loads in flight)
    for (; p + 2 <= end; p += 2) {
        int tokA = feat[p], tokB = feat[p + 1];
        const float4* rA = (const float4*)(emb + (size_t)tokA * D_DIM);
        const float4* rB = (const float4*)(emb + (size_t)tokB * D_DIM);
        float4 vA0 = rA[lane], vA1 = rA[lane + 32];
        float4 vB0 = rB[lane], vB1 = rB[lane + 32];
        a0.x += vA0.x + vB0.x; a0.y += vA0.y + vB0.y;
        a0.z += vA0.z + vB0.z; a0.w += vA0.w + vB0.w;
        a1.x += vA1.x + vB1.x; a1.y += vA1.y + vB1.y;
        a1.z += vA1.z + vB1.z; a1.w += vA1.w + vB1.w;
    }
    for (; p < end; p++) {
        int tok = feat[p];
        const float4* row = (const float4*)(emb + (size_t)tok * D_DIM);
        float4 v0 = row[lane], v1 = row[lane + 32];
        a0.x += v0.x; a0.y += v0.y; a0.z += v0.z; a0.w += v0.w;
        a1.x += v1.x; a1.y += v1.y; a1.z += v1.z; a1.w += v1.w;
    }
    float inv = 1.0f / (float)(end - start);
    a0.x *= inv; a0.y *= inv; a0.z *= inv; a0.w *= inv;
    a1.x *= inv; a1.y *= inv; a1.z *= inv; a1.w *= inv;

    // evict-first stores: men_emb is read exactly once (by k3a); keep emb in L2
    float4* mrow = (float4*)(g_men_emb + (size_t)m * D_DIM);
    __stcs(&mrow[lane],      a0);
    __stcs(&mrow[lane + 32], a1);

    const float4* w = (const float4*)(lw + (size_t)t * D_DIM);
    float4 w0 = w[lane];
    float4 w1 = w[lane + 32];
    float d = a0.x * w0.x + a0.y * w0.y + a0.z * w0.z + a0.w * w0.w
            + a1.x * w1.x + a1.y * w1.y + a1.z * w1.z + a1.w * w1.w;
    #pragma unroll
    for (int off = 16; off; off >>= 1) d += __shfl_xor_sync(0xffffffffu, d, off);
    if (lane == 0) g_sel[m] = d;
}

// ---------------------------------------------------------------------------
// K3a: one 256-thread block per bag. Fused softmax (warp 0) + weighted sum.
//      bag_emb[b,d] = sum_m exp(sel[m]-mx)/sum * men_emb[m,d]
// ---------------------------------------------------------------------------
__global__ void k3a_bagemb(const int* __restrict__ scope,
                           float*     __restrict__ bag_emb) {
    int b = blockIdx.x;
    int tid = threadIdx.x, lane = tid & 31, warp = tid >> 5;
    int s = scope[b], e = scope[b + 1];

    __shared__ float s_mx, s_inv;
    if (warp == 0) {
        float mx = -INFINITY;
        for (int m = s + lane; m < e; m += 32) mx = fmaxf(mx, g_sel[m]);
        #pragma unroll
        for (int off = 16; off; off >>= 1)
            mx = fmaxf(mx, __shfl_xor_sync(0xffffffffu, mx, off));
        float sum = 0.f;
        for (int m = s + lane; m < e; m += 32) sum += expf(g_sel[m] - mx);
        #pragma unroll
        for (int off = 16; off; off >>= 1)
            sum += __shfl_xor_sync(0xffffffffu, sum, off);
        if (lane == 0) { s_mx = mx; s_inv = 1.0f / sum; }
    }
    __syncthreads();
    float mx = s_mx, inv = s_inv;

    float acc = 0.f;
    int m = s;
    for (; m + 4 <= e; m += 4) {
        float w0 = expf(g_sel[m]     - mx);
        float w1 = expf(g_sel[m + 1] - mx);
        float w2 = expf(g_sel[m + 2] - mx);
        float w3 = expf(g_sel[m + 3] - mx);
        float v0 = __ldcs(&g_men_emb[(size_t)(m)     * D_DIM + tid]);
        float v1 = __ldcs(&g_men_emb[(size_t)(m + 1) * D_DIM + tid]);
        float v2 = __ldcs(&g_men_emb[(size_t)(m + 2) * D_DIM + tid]);
        float v3 = __ldcs(&g_men_emb[(size_t)(m + 3) * D_DIM + tid]);
        acc += w0 * v0 + w1 * v1 + w2 * v2 + w3 * v3;
    }
    for (; m < e; m++)
        acc += expf(g_sel[m] - mx) * __ldcs(&g_men_emb[(size_t)m * D_DIM + tid]);

    bag_emb[(size_t)b * D_DIM + tid] = acc * inv;
}

// ---------------------------------------------------------------------------
// K3b: register-tiled GEMM  out[5000,100] = bag_emb[5000,256] @ W[100,256]^T
//      Tile: 32 bags x 128 k (k padded, guarded). 256 threads:
//      kt = tid&31 owns k = kt+32j (j<4), bt = tid>>5 owns 4 bags.
//      4x4 register tile -> 0.5 smem loads per FMA; all accesses conflict-free.
// ---------------------------------------------------------------------------
#define GEMM_BM 32
__global__ void k3b_gemm(const float* __restrict__ A,
                         const float* __restrict__ W,
                         float*       __restrict__ out) {
    __shared__ float sA[32][33];    // [d][bag]   (pad 33: conflict-free)
    __shared__ float sW[128][33];   // [k][d]     (pad 33: conflict-free)
    int tid = threadIdx.x;
    int kt = tid & 31;
    int bt = tid >> 5;              // 0..7, each owns 4 bags
    int bag0 = blockIdx.x * GEMM_BM;

    float acc[4][4];
    #pragma unroll
    for (int r = 0; r < 4; r++)
        #pragma unroll
        for (int j = 0; j < 4; j++) acc[r][j] = 0.f;

    for (int d0 = 0; d0 < D_DIM; d0 += 32) {
        // A tile: 32 bags x 32 d, 1 float4 per thread
        {
            int b = tid >> 3, x = tid & 7;
            int bag = bag0 + b;
            float4 v = (bag < B_BAG)
                ? *(const float4*)(A + (size_t)bag * D_DIM + d0 + 4 * x)
                : make_float4(0.f, 0.f, 0.f, 0.f);
            sA[4 * x + 0][b] = v.x; sA[4 * x + 1][b] = v.y;
            sA[4 * x + 2][b] = v.z; sA[4 * x + 3][b] = v.w;
        }
        // W tile: 128 k x 32 d, 4 float4 per thread (k>=100 zero-filled)
        #pragma unroll
        for (int i = 0; i < 4; i++) {
            int idx = tid + 256 * i;
            int k = idx >> 3, x = idx & 7;
            float4 v = (k < K_TYP)
                ? *(const float4*)(W + (size_t)k * D_DIM + d0 + 4 * x)
                : make_float4(0.f, 0.f, 0.f, 0.f);
            sW[k][4 * x + 0] = v.x; sW[k][4 * x + 1] = v.y;
            sW[k][4 * x + 2] = v.z; sW[k][4 * x + 3] = v.w;
        }
        __syncthreads();

        #pragma unroll
        for (int d = 0; d < 32; d++) {
            float a0 = sA[d][bt * 4 + 0];
            float a1 = sA[d][bt * 4 + 1];
            float a2 = sA[d][bt * 4 + 2];
            float a3 = sA[d][bt * 4 + 3];
            float w0 = sW[kt      ][d];
            float w1 = sW[kt + 32 ][d];
            float w2 = sW[kt + 64 ][d];
            float w3 = sW[kt + 96 ][d];
            acc[0][0] += a0 * w0; acc[0][1] += a0 * w1; acc[0][2] += a0 * w2; acc[0][3] += a0 * w3;
            acc[1][0] += a1 * w0; acc[1][1] += a1 * w1; acc[1][2] += a1 * w2; acc[1][3] += a1 * w3;
            acc[2][0] += a2 * w0; acc[2][1] += a2 * w1; acc[2][2] += a2 * w2; acc[2][3] += a2 * w3;
            acc[3][0] += a3 * w0; acc[3][1] += a3 * w1; acc[3][2] += a3 * w2; acc[3][3] += a3 * w3;
        }
        __syncthreads();
    }

    #pragma unroll
    for (int r = 0; r < 4; r++) {
        int bag = bag0 + bt * 4 + r;
        if (bag >= B_BAG) continue;
        #pragma unroll
        for (int j = 0; j < 4; j++) {
            int k = kt + 32 * j;
            if (k < K_TYP) out[(size_t)bag * K_TYP + k] = acc[r][j];
        }
    }
}

// ---------------------------------------------------------------------------
extern "C" void kernel_launch(void* const* d_in, const int* in_sizes, int n_in,
                              void* d_out, int out_size) {
    const int*   feature_seq    = (const int*)  d_in[0];
    const int*   offset_seq     = (const int*)  d_in[1];
    const int*   scope          = (const int*)  d_in[2];
    const float* typeTensor     = (const float*)d_in[3];
    const float* word_embedding = (const float*)d_in[4];
    const float* linear_weight  = (const float*)d_in[5];
    float*       out            = (float*)d_out;

    int*   tidx = nullptr;
    float* bagE = nullptr;
    cudaGetSymbolAddress((void**)&tidx, g_type_idx);
    cudaGetSymbolAddress((void**)&bagE, g_bag_emb);

    k0_argmax<<<(B_BAG + 7) / 8, 256>>>(typeTensor, tidx);
    k1_mention<<<(M_MEN + 7) / 8, 256>>>(feature_seq, offset_seq, scope,
                                         word_embedding, linear_weight, tidx);
    k3a_bagemb<<<B_BAG, 256>>>(scope, bagE);
    k3b_gemm<<<(B_BAG + GEMM_BM - 1) / GEMM_BM, 256>>>(bagE, linear_weight, out);
}